// round 3
// baseline (speedup 1.0000x reference)
#include <cuda_runtime.h>
#include <math_constants.h>

// DilateErode tropical matmul, unified max-plus:
//   dilated[b,n] = max_f ( xb[b,f] + D[f,n] )
//   eroded [b,n] = -max_f( (-xb[b,f]) + E[f,n] )   (bit-exact vs fp32 ref)
//
// float4-typed smem (guaranteed LDS.128), k-chunked x layout (xa regs reused
// over 4 kk), XOR swizzle in float4 units, software-pipelined inner loop,
// double-buffered tiles with single barrier + register LDG prefetch.

#define Fdim 1024
#define Bdim 1024
#define NW   256
#define OUTC 512
#define BM   64
#define BN   64
#define KB   32
#define NT   (Fdim / KB)   // 32
#define QG   (KB / 4)      // 8 k-groups of 4

__global__ __launch_bounds__(256, 1)
void trop_kernel(const float* __restrict__ x,
                 const float* __restrict__ dil,
                 const float* __restrict__ ero,
                 float* __restrict__ out)
{
    // xsT[buf][q][col4] : float4 = (sign-applied) x[row, k0+4q .. 4q+3], col4 = row ^ q
    // ws [buf][k][c4]   : float4 = W[k0+k, wColBase + 4*c4 .. +3]
    __shared__ float4 xsT[2][QG][BM];      // 16 KB
    __shared__ float4 ws [2][KB][BN / 4];  // 16 KB

    const int tid = threadIdx.x;
    const int tx  = tid & 15;          // 4 output cols
    const int ty  = tid >> 4;          // 4 output rows
    const int rowBase = blockIdx.y * BM;

    const bool erode     = (blockIdx.x < 4);
    const unsigned smask = erode ? 0x80000000u : 0u;
    const float* __restrict__ W = erode ? ero : dil;
    const int wColBase   = (blockIdx.x & 3) * BN;
    const int outColBase = blockIdx.x * BN;

    // x loader: 512 float4/tile, 2 per thread.  q = tid&7, row = tid>>3 (+32)
    const int xq    = tid & 7;
    const int xrow0 = tid >> 3;              // 0..31
    const int xc0   = xrow0 ^ xq;            // swizzled col4
    const int xc1   = (xrow0 + 32) ^ xq;
    const float4* xp = (const float4*)(x + (size_t)(rowBase + xrow0) * Fdim) + xq;
    const int xstride4 = 32 * (Fdim / 4);    // 32 rows in float4 units

    // w loader: 512 float4/tile, 2 per thread.  c4 = tid&15, k = tid>>4 (+16)
    const int wc4 = tid & 15;
    const int wk0 = tid >> 4;                // 0..15
    const float4* wp = (const float4*)(W + (size_t)wk0 * NW + wColBase) + wc4;
    const int wstride4 = 16 * (NW / 4);      // 16 k-rows in float4 units

    // prefetch tile 0
    float4 xr0 = xp[0];
    float4 xr1 = xp[xstride4];
    float4 wr0 = wp[0];
    float4 wr1 = wp[wstride4];

    float acc[4][4];
#pragma unroll
    for (int i = 0; i < 4; ++i)
#pragma unroll
        for (int j = 0; j < 4; ++j)
            acc[i][j] = -CUDART_INF_F;

    for (int t = 0; t < NT; ++t) {
        const int buf = t & 1;

        // ---- store prefetched tile (sign flip on x via 4 LOP3 per float4) ----
        {
            uint4 u0 = *(uint4*)&xr0, u1 = *(uint4*)&xr1;
            u0.x ^= smask; u0.y ^= smask; u0.z ^= smask; u0.w ^= smask;
            u1.x ^= smask; u1.y ^= smask; u1.z ^= smask; u1.w ^= smask;
            xsT[buf][xq][xc0] = *(float4*)&u0;
            xsT[buf][xq][xc1] = *(float4*)&u1;
            ws[buf][wk0     ][wc4] = wr0;
            ws[buf][wk0 + 16][wc4] = wr1;
        }

        // ---- prefetch next tile's globals (hidden under compute) ----
        if (t + 1 < NT) {
            xp += KB / 4;
            wp += KB * (NW / 4);
            xr0 = xp[0];
            xr1 = xp[xstride4];
            wr0 = wp[0];
            wr1 = wp[wstride4];
        }
        __syncthreads();

        // ---- compute: 8 q-groups of 4 kk, x regs pipelined one group ahead ----
        float4 xa[4], xn[4];
#pragma unroll
        for (int i = 0; i < 4; ++i)
            xa[i] = xsT[buf][0][(ty * 4 + i) ^ 0];

#pragma unroll
        for (int q = 0; q < QG; ++q) {
            const int qn = (q + 1) & (QG - 1);
#pragma unroll
            for (int i = 0; i < 4; ++i)
                xn[i] = xsT[buf][qn][(ty * 4 + i) ^ qn];

#pragma unroll
            for (int d = 0; d < 4; ++d) {
                float4 wv = ws[buf][q * 4 + d][tx];
                float wa[4] = {wv.x, wv.y, wv.z, wv.w};
                float xv[4];
                xv[0] = (d == 0) ? xa[0].x : (d == 1) ? xa[0].y : (d == 2) ? xa[0].z : xa[0].w;
                xv[1] = (d == 0) ? xa[1].x : (d == 1) ? xa[1].y : (d == 2) ? xa[1].z : xa[1].w;
                xv[2] = (d == 0) ? xa[2].x : (d == 1) ? xa[2].y : (d == 2) ? xa[2].z : xa[2].w;
                xv[3] = (d == 0) ? xa[3].x : (d == 1) ? xa[3].y : (d == 2) ? xa[3].z : xa[3].w;
#pragma unroll
                for (int i = 0; i < 4; ++i)
#pragma unroll
                    for (int j = 0; j < 4; ++j)
                        acc[i][j] = fmaxf(acc[i][j], xv[i] + wa[j]);
            }
#pragma unroll
            for (int i = 0; i < 4; ++i)
                xa[i] = xn[i];
        }
        __syncthreads();   // protect buf reuse (double buffer => every other ok,
                           // but smem written at top is read same iter; keep it)
    }

    // ---- bias feature f = 1024 (xb contribution is 0) ----
    {
        float4 wb = *(const float4*)&W[(size_t)Fdim * NW + wColBase + (tx << 2)];
        float wa[4] = {wb.x, wb.y, wb.z, wb.w};
#pragma unroll
        for (int i = 0; i < 4; ++i)
#pragma unroll
            for (int j = 0; j < 4; ++j)
                acc[i][j] = fmaxf(acc[i][j], wa[j]);
    }

    // ---- store, undoing the sign flip for the erosion half ----
#pragma unroll
    for (int i = 0; i < 4; ++i) {
        int row = rowBase + ty * 4 + i;
        uint4 o;
        o.x = __float_as_uint(acc[i][0]) ^ smask;
        o.y = __float_as_uint(acc[i][1]) ^ smask;
        o.z = __float_as_uint(acc[i][2]) ^ smask;
        o.w = __float_as_uint(acc[i][3]) ^ smask;
        *(uint4*)&out[(size_t)row * OUTC + outColBase + (tx << 2)] = o;
    }
}

extern "C" void kernel_launch(void* const* d_in, const int* in_sizes, int n_in,
                              void* d_out, int out_size)
{
    const float* x   = (const float*)d_in[0];   // (1024, 1024)
    const float* dil = (const float*)d_in[1];   // (1025, 256)
    const float* ero = (const float*)d_in[2];   // (1025, 256)
    float* out = (float*)d_out;                 // (1024, 512) = [eroded | dilated]

    dim3 grid(OUTC / BN, Bdim / BM);            // (8, 16) = 128 blocks
    trop_kernel<<<grid, 256>>>(x, dil, ero, out);
}